// round 3
// baseline (speedup 1.0000x reference)
#include <cuda_runtime.h>

// Chunked state-space formulation:
//   T = 64 chunk, M = 64 chunks, n = 64 state, CH = 128 channels, BATCH = 16.
//   y[b,c,m*64+jj] = sum_{j'<=jj} k[jj-j',c] * u[b,m*64+j']      (intra-chunk Toeplitz)
//                  + (C A^{jj+1} x[b,m])[c]                      (inter-chunk via state)
//                  + D[c]*u[b,t]
// Single GEMM: Y(8192x1024) = [Ktoep | Ghat](8192x128) @ [U ; X](128x1024)

#define PADA 129

__device__ float g_P[2][64*64];      // ping-pong powers of A_bar
__device__ float g_W[64][64];        // W[j] = A_bar^j B_bar
__device__ float g_G[64][128*64];    // Ghat[jj] = C A_bar^{jj+1}  (row-major [c][s])
__device__ float g_ktab[64][128];    // k[j][c] = C[c,:] . W[j]
__device__ float g_Z[128][1024];     // RHS: rows 0..63 = u chunks, 64..127 = states

// ---------------------------------------------------------------------------
// K1: bilinear discretization. E = I - dt/2 A (lower-triangular, diag>=1),
// Gauss-Jordan on augmented [E | I+dt/2 A | dt*B] -> [I | A_bar | B_bar].
// Also Ghat[0] = C @ A_bar.
// ---------------------------------------------------------------------------
__global__ __launch_bounds__(256) void k_setup(const float* __restrict__ A,
                                               const float* __restrict__ B,
                                               const float* __restrict__ C,
                                               const float* __restrict__ dtp) {
    __shared__ float aug[64][132];
    __shared__ float fac[64];
    __shared__ float pivinv;
    int tid = threadIdx.x;
    float dt = dtp[0], hd = 0.5f * dt;
    for (int idx = tid; idx < 4096; idx += 256) {
        int i = idx >> 6, j = idx & 63;
        float a = A[idx];
        float d = (i == j) ? 1.f : 0.f;
        aug[i][j]      = d - hd * a;
        aug[i][64 + j] = d + hd * a;
    }
    for (int i = tid; i < 64; i += 256) aug[i][128] = dt * B[i];
    __syncthreads();
    for (int k = 0; k < 64; k++) {
        if (tid == 0) pivinv = 1.f / aug[k][k];
        __syncthreads();
        for (int j = tid; j < 129; j += 256) aug[k][j] *= pivinv;
        __syncthreads();
        for (int i = tid; i < 64; i += 256) fac[i] = (i == k) ? 0.f : aug[i][k];
        __syncthreads();
        for (int idx = tid; idx < 64 * 129; idx += 256) {
            int i = idx / 129, j = idx - i * 129;
            aug[i][j] -= fac[i] * aug[k][j];
        }
        __syncthreads();
    }
    for (int idx = tid; idx < 4096; idx += 256) {
        int i = idx >> 6, j = idx & 63;
        g_P[0][idx] = aug[i][64 + j];                // A_bar
    }
    for (int i = tid; i < 64; i += 256) g_W[0][i] = aug[i][128];   // B_bar
    // Ghat[0] = C @ A_bar
    for (int idx = tid; idx < 8192; idx += 256) {
        int c = idx >> 6, t = idx & 63;
        float acc = 0.f;
        #pragma unroll 8
        for (int s = 0; s < 64; s++) acc += C[c * 64 + s] * aug[s][64 + t];
        g_G[0][idx] = acc;
    }
}

// ---------------------------------------------------------------------------
// K2..K7: log-doubling round r (r=0..5). Pcur = A_bar^{2^r} (in g_P[r&1]).
//   block 0      : Pnext = Pcur^2 ; W[j+2^r] = Pcur @ W[j]
//   blocks 1..   : Ghat[j+2^r] = Ghat[j] @ Pcur   (4 blocks per product)
// After r=5: Ghat[0..63], W[0..63], g_P[0] = A_bar^64.
// ---------------------------------------------------------------------------
__global__ __launch_bounds__(256) void k_round(int r) {
    const float* __restrict__ Pcur = g_P[r & 1];
    __shared__ float Ps[64][65];
    int tid = threadIdx.x;
    for (int idx = tid; idx < 4096; idx += 256) Ps[idx >> 6][idx & 63] = Pcur[idx];
    __syncthreads();
    int half = 1 << r;
    int bid = blockIdx.x;
    if (bid == 0) {
        float* Pn = g_P[(r + 1) & 1];
        for (int idx = tid; idx < 4096; idx += 256) {
            int i = idx >> 6, t = idx & 63;
            float acc = 0.f;
            #pragma unroll 8
            for (int s = 0; s < 64; s++) acc += Ps[i][s] * Ps[s][t];
            Pn[idx] = acc;
        }
        for (int idx = tid; idx < half * 64; idx += 256) {
            int j = idx >> 6, i = idx & 63;
            float acc = 0.f;
            #pragma unroll 8
            for (int s = 0; s < 64; s++) acc += Ps[i][s] * g_W[j][s];
            g_W[j + half][i] = acc;
        }
    } else {
        int p = bid - 1;
        int j = p >> 2, piece = p & 3;
        if (j < half) {
            const float* __restrict__ Gj = g_G[j];
            float* Go = g_G[j + half];
            int r0 = piece * 32;
            for (int idx = tid; idx < 2048; idx += 256) {
                int rr = r0 + (idx >> 6), t = idx & 63;
                float acc = 0.f;
                #pragma unroll 8
                for (int s = 0; s < 64; s++) acc += Gj[rr * 64 + s] * Ps[s][t];
                Go[rr * 64 + t] = acc;
            }
        }
    }
}

// ---------------------------------------------------------------------------
// K8: blocks 0..15: per-batch chunk-input projection S = F @ u_chunks, then
//     serial state scan x_{m+1} = A_T x_m + S[m]; write Z (u rows + state rows).
//     blocks 16..31: k-table k[j][c] = C[c,:].W[j].
// ---------------------------------------------------------------------------
__global__ __launch_bounds__(256) void k_prep(const float* __restrict__ u,
                                              const float* __restrict__ C) {
    extern __shared__ float sm[];
    int tid = threadIdx.x, bid = blockIdx.x;
    if (bid < 16) {
        float* us  = sm;                  // [64][66]  u chunks, padded
        float* Fs  = sm + 64 * 66;        // [64][65]  Fs[i][s] = W[63-i][s]
        float* Sm  = Fs + 64 * 65;        // [64][65]  S[m][s]
        float* ATs = Sm + 64 * 65;        // [64][65]  A_bar^64
        float* xv  = ATs + 64 * 65;       // [64]
        float* part = xv + 64;            // [4][64]
        int b = bid;
        for (int idx = tid; idx < 4096; idx += 256) {
            int m = idx >> 6, j = idx & 63;
            us[m * 66 + j] = u[b * 4096 + idx];
        }
        for (int idx = tid; idx < 4096; idx += 256) {
            int i = idx >> 6, s = idx & 63;
            Fs[i * 65 + s]  = g_W[63 - i][s];
            ATs[i * 65 + s] = g_P[0][idx];
        }
        __syncthreads();
        // S[m][s] = sum_i A^{63-i} B_bar [s] * u[m*64+i]
        for (int idx = tid; idx < 4096; idx += 256) {
            int m = idx >> 6, s = idx & 63;
            float acc = 0.f;
            #pragma unroll 8
            for (int i = 0; i < 64; i++) acc += Fs[i * 65 + s] * us[m * 66 + i];
            Sm[m * 65 + s] = acc;
        }
        // u rows of Z (coalesced along m)
        for (int idx = tid; idx < 4096; idx += 256) {
            int j = idx >> 6, m = idx & 63;
            g_Z[j][b * 64 + m] = us[m * 66 + j];
        }
        if (tid < 64) xv[tid] = 0.f;
        __syncthreads();
        // serial scan over 64 chunks; 4-way split dot per state element
        int s = tid & 63, q = tid >> 6;
        for (int m = 0; m < 64; m++) {
            if (q == 0) g_Z[64 + s][b * 64 + m] = xv[s];   // state at chunk start
            float acc = 0.f;
            #pragma unroll
            for (int s2 = q * 16; s2 < q * 16 + 16; s2++) acc += ATs[s * 65 + s2] * xv[s2];
            part[q * 64 + s] = acc;
            __syncthreads();
            if (q == 0)
                xv[s] = part[s] + part[64 + s] + part[128 + s] + part[192 + s] + Sm[m * 65 + s];
            __syncthreads();
        }
    } else {
        __shared__ float Ws[4][64];
        int j0 = (bid - 16) * 4;
        for (int idx = tid; idx < 256; idx += 256)
            Ws[idx >> 6][idx & 63] = g_W[j0 + (idx >> 6)][idx & 63];
        __syncthreads();
        for (int idx = tid; idx < 512; idx += 256) {
            int jj = idx >> 7, c = idx & 127;
            float acc = 0.f;
            #pragma unroll 8
            for (int s = 0; s < 64; s++) acc += C[c * 64 + s] * Ws[jj][s];
            g_ktab[j0 + jj][c] = acc;
        }
    }
}

// ---------------------------------------------------------------------------
// K9: main GEMM 8192x1024x128 with fused A-tile construction and epilogue.
// Grid (8 ntiles, 64 mtiles), 128x128 tiles, 8x8 register micro-tiles.
// Row R = c*64+jj, Col N = b*64+m. A-tile built in smem:
//   cols 0..63  : Toeplitz k[jj-j',c]
//   cols 64..127: Ghat[jj][c][s]
// Epilogue: out[b][c][m*64+jj] = acc + D[c]*u  (u read back from Zs rows 0..63).
// ---------------------------------------------------------------------------
__global__ __launch_bounds__(256) void k_gemm(const float* __restrict__ D,
                                              float* __restrict__ out) {
    extern __shared__ float sm[];
    float* As = sm;                    // [128][PADA]  (K-major: As[k][m])
    float* Zs = sm + 128 * PADA;       // [128][PADA]  (Zs[k][n])
    float* kt = Zs + 128 * PADA;       // [64][2]
    int tid = threadIdx.x;
    int ntile = blockIdx.x, mtile = blockIdx.y;
    int c0 = mtile * 2, n0 = ntile * 128;

    for (int idx = tid; idx < 128; idx += 256) kt[idx] = g_ktab[idx >> 1][c0 + (idx & 1)];
    // Ghat half of A-tile
    for (int idx = tid; idx < 8192; idx += 256) {
        int m = idx >> 6, s2 = idx & 63;
        int jj = m & 63, cc = m >> 6;
        As[(64 + s2) * PADA + m] = g_G[jj][(c0 + cc) * 64 + s2];
    }
    // Z tile
    for (int idx = tid; idx < 16384; idx += 256) {
        int k = idx >> 7, n = idx & 127;
        Zs[k * PADA + n] = g_Z[k][n0 + n];
    }
    __syncthreads();   // kt ready
    // Toeplitz half of A-tile
    for (int idx = tid; idx < 8192; idx += 256) {
        int m = idx >> 6, k = idx & 63;
        int jj = m & 63, cc = m >> 6;
        As[k * PADA + m] = (k <= jj) ? kt[((jj - k) << 1) + cc] : 0.f;
    }
    __syncthreads();

    int tr = tid & 15, tc = tid >> 4;
    float acc[8][8];
    #pragma unroll
    for (int i = 0; i < 8; i++)
        #pragma unroll
        for (int j = 0; j < 8; j++) acc[i][j] = 0.f;

    #pragma unroll 4
    for (int k = 0; k < 128; k++) {
        float a[8], z[8];
        #pragma unroll
        for (int i = 0; i < 8; i++) a[i] = As[k * PADA + tr + 16 * i];
        #pragma unroll
        for (int j = 0; j < 8; j++) z[j] = Zs[k * PADA + tc + 16 * j];
        #pragma unroll
        for (int i = 0; i < 8; i++)
            #pragma unroll
            for (int j = 0; j < 8; j++) acc[i][j] += a[i] * z[j];
    }

    float D0 = D[c0], D1 = D[c0 + 1];
    #pragma unroll
    for (int i = 0; i < 8; i++) {
        int m = tr + 16 * i, jj = m & 63, cc = m >> 6;
        int c = c0 + cc;
        float Dv = cc ? D1 : D0;
        #pragma unroll
        for (int j = 0; j < 8; j++) {
            int n = tc + 16 * j;
            int gn = n0 + n, b = gn >> 6, mm = gn & 63;
            int t = mm * 64 + jj;
            float uval = Zs[jj * PADA + n];
            out[(b * 128 + c) * 4096 + t] = acc[i][j] + Dv * uval;
        }
    }
}

// ---------------------------------------------------------------------------
extern "C" void kernel_launch(void* const* d_in, const int* in_sizes, int n_in,
                              void* d_out, int out_size) {
    const float *u = 0, *A = 0, *B = 0, *C = 0, *D = 0, *dt = 0;
    for (int i = 0; i < n_in; i++) {
        const float* p = (const float*)d_in[i];
        switch (in_sizes[i]) {
            case 65536: u = p;  break;   // (16, 4096)
            case 4096:  A = p;  break;   // (64, 64)
            case 64:    B = p;  break;   // (64, 1)
            case 8192:  C = p;  break;   // (128, 64)
            case 128:   D = p;  break;   // (128, 1)
            case 1:     dt = p; break;
        }
    }
    const int prep_smem = (64 * 66 + 3 * 64 * 65 + 64 + 256) * sizeof(float);   // 68096
    const int gemm_smem = (2 * 128 * PADA + 128) * sizeof(float);               // 132608
    cudaFuncSetAttribute(k_prep, cudaFuncAttributeMaxDynamicSharedMemorySize, prep_smem);
    cudaFuncSetAttribute(k_gemm, cudaFuncAttributeMaxDynamicSharedMemorySize, gemm_smem);

    k_setup<<<1, 256>>>(A, B, C, dt);
    for (int r = 0; r < 6; r++) k_round<<<129, 256>>>(r);
    k_prep<<<32, 256, prep_smem>>>(u, C);
    k_gemm<<<dim3(8, 64), 256, gemm_smem>>>(D, (float*)d_out);
}